// round 17
// baseline (speedup 1.0000x reference)
#include <cuda_runtime.h>
#include <cstdint>
#include <cstddef>

typedef unsigned long long U64;

#define KC 32

// ---------------- persistent device scratch ----------------
__device__ __align__(16) float g_xT[64 * 256 * 128];    // [t][d][2b] dup  8 MB
__device__ __align__(16) float g_h[3 * 1024 * 128];     // [layer][hcol][2b] dup
__device__ __align__(16) float g_c[3 * 1024 * 64];      // [layer][hcol][b]
__device__ __align__(16) float g_z[4ull * 64 * 64 * 64];// [q][blk][row][64col] 4 MB
__device__ __align__(16) float g_outs[64 * 1024 * 64];  // [t][hcol][b] 16 MB
__device__ int g_cnt[64];                               // split-K arrival counters

// ---------------- helpers ----------------
__device__ __forceinline__ U64 fma2(U64 a, U64 b, U64 c) {
    U64 d; asm("fma.rn.f32x2 %0, %1, %2, %3;" : "=l"(d) : "l"(a), "l"(b), "l"(c));
    return d;
}
__device__ __forceinline__ U64 dupf(float x) {
    U64 r; unsigned u = __float_as_uint(x);
    asm("mov.b64 %0, {%1, %1};" : "=l"(r) : "r"(u));
    return r;
}
__device__ __forceinline__ void unpk(U64 v, float& lo, float& hi) {
    unsigned a, b;
    asm("mov.b64 {%0, %1}, %2;" : "=r"(a), "=r"(b) : "l"(v));
    lo = __uint_as_float(a); hi = __uint_as_float(b);
}
__device__ __forceinline__ void cpa16(uint32_t s, const void* g) {
    asm volatile("cp.async.cg.shared.global [%0], [%1], 16;" :: "r"(s), "l"(g));
}
__device__ __forceinline__ float sigm(float x) { return 1.f / (1.f + expf(-x)); }

// ---------------- pre-transforms ----------------
// x [b][t][d] -> xT_dup [t][d][2b] (each value duplicated)
__global__ void transpose_x(const float* __restrict__ x, float* __restrict__ xT) {
    int idx = blockIdx.x * 256 + threadIdx.x;    // 1,048,576
    int b = idx >> 14, t = (idx >> 8) & 63, d = idx & 255;
    float v = x[idx];
    *(float2*)&xT[((size_t)(t * 256 + d)) * 128 + 2 * b] = make_float2(v, v);
}

// h0/c0 [L][1][1024] broadcast: h dup'd, c normal
__global__ void init_hc(const float* __restrict__ h0, const float* __restrict__ c0,
                        float* __restrict__ hb, float* __restrict__ cb) {
    int idx = blockIdx.x * 256 + threadIdx.x;    // 3*1024*64 = 196608
    int l = idx >> 16, rem = idx & 65535, k = rem >> 6, b = rem & 63;
    float hv = h0[l * 1024 + k];
    *(float2*)&hb[((size_t)(l * 1024 + k)) * 128 + 2 * b] = make_float2(hv, hv);
    cb[idx] = c0[l * 1024 + k];
}

// ---------------- fused GEMM (split-K=4) + last-CTA cell epilogue ----------------
// Partial z over two k-segments (a0/w0 length K0, a1/w1 length 1024); activations
// are in duplicated layout [k][2b]. CTA covers 64 gate-cols (4 gates x 16 hcols,
// same hcols across gates) x 64 rows. Thread: 8 cols x 2 rows, col-pair packed
// accumulators (f32x2 lanes = two adjacent columns).
// Last of the 4 K-quarter CTAs per col-tile reduces and runs the cell update:
// gate order (f,i,g,o); peephole Wc on ALL 4 gates (reference quirk).
__global__ void __launch_bounds__(256, 2) lstm_gemm(
    const float* __restrict__ a0, const float* __restrict__ w0, int K0,
    const float* __restrict__ a1, const float* __restrict__ w1,
    float* __restrict__ zp,
    const float* __restrict__ wc, const float* __restrict__ bias,
    float* __restrict__ cst, float* __restrict__ hdup, float* __restrict__ outdup)
{
    extern __shared__ __align__(16) float smem[];
    float* Asm = smem;                 // [3][KC][128]  48 KB
    float* Wsm = smem + 3 * KC * 128;  // [3][KC][64]   24 KB
    __shared__ int s_last;

    const int tid = threadIdx.x;
    const int blk = blockIdx.x;        // col tile: hcols blk*16..+15, all 4 gates
    const int q   = blockIdx.y;        // K quarter
    const int rgp = tid & 31;          // rows 2*rgp, 2*rgp+1
    const int cg  = tid >> 5;          // cols cg*8..cg*8+7 (warp-uniform)
    const int nq  = (K0 + 1024) >> 7;  // chunks per quarter
    const int base = q * nq;

    uint32_t sA = (uint32_t)__cvta_generic_to_shared(Asm);
    uint32_t sW = (uint32_t)__cvta_generic_to_shared(Wsm);

    U64 acc[8];
    #pragma unroll
    for (int i = 0; i < 8; ++i) acc[i] = 0;

    auto issue = [&](int ch, int buf) {
        int kb = (base + ch) << 5;
        const float* ab; const float* wb; int kk0;
        if (kb < K0) { ab = a0; wb = w0; kk0 = kb; }
        else         { ab = a1; wb = w1; kk0 = kb - K0; }
        // A tile (dup): 32k x 128 floats = 1024 x 16B -> 4 per thread
        #pragma unroll
        for (int j = 0; j < 4; ++j) {
            int i = tid + j * 256;
            int k = i >> 5, c = i & 31;
            cpa16(sA + (uint32_t)((buf * KC * 128 + k * 128 + c * 4) * 4),
                  ab + (size_t)(kk0 + k) * 128 + c * 4);
        }
        // W tile: 32k x 64 cols (4 gates x 16 hcols) = 512 x 16B -> 2 per thread
        #pragma unroll
        for (int j = 0; j < 2; ++j) {
            int i = tid + j * 256;
            int k = i >> 4, s = i & 15, g = s >> 2, off = (s & 3) << 2;
            cpa16(sW + (uint32_t)((buf * KC * 64 + k * 64 + g * 16 + off) * 4),
                  wb + (size_t)(kk0 + k) * 4096 + (size_t)g * 1024 + blk * 16 + off);
        }
        asm volatile("cp.async.commit_group;");
    };

    issue(0, 0);
    issue(1, 1);

    for (int ch = 0; ch < nq; ++ch) {
        if (ch + 1 < nq) asm volatile("cp.async.wait_group 1;");
        else             asm volatile("cp.async.wait_group 0;");
        __syncthreads();
        if (ch + 2 < nq) issue(ch + 2, (ch + 2) % 3);

        const float* Ab = Asm + (ch % 3) * KC * 128;
        const float* Wb = Wsm + (ch % 3) * KC * 64;
        #pragma unroll
        for (int kk = 0; kk < KC; ++kk) {
            // two rows' duplicated activations: one LDS.128
            ulonglong2 ad = *(const ulonglong2*)(Ab + kk * 128 + rgp * 4);
            // eight columns' weights: two broadcast LDS.128 (4 col-pairs)
            ulonglong2 w01 = *(const ulonglong2*)(Wb + kk * 64 + cg * 8);
            ulonglong2 w23 = *(const ulonglong2*)(Wb + kk * 64 + cg * 8 + 4);
            acc[0] = fma2(ad.x, w01.x, acc[0]);   // row0, cols c0,c1
            acc[1] = fma2(ad.y, w01.x, acc[1]);   // row1, cols c0,c1
            acc[2] = fma2(ad.x, w01.y, acc[2]);   // row0, cols c2,c3
            acc[3] = fma2(ad.y, w01.y, acc[3]);
            acc[4] = fma2(ad.x, w23.x, acc[4]);   // row0, cols c4,c5
            acc[5] = fma2(ad.y, w23.x, acc[5]);
            acc[6] = fma2(ad.x, w23.y, acc[6]);   // row0, cols c6,c7
            acc[7] = fma2(ad.y, w23.y, acc[7]);
        }
    }

    // ---- store partials: zp[q][blk][row][col], col contiguous ----
    {
        float* zr = zp + (((size_t)q * 64 + blk) * 64) * 64;
        int r0 = 2 * rgp, cb0 = cg * 8;
        ulonglong2 v;
        v.x = acc[0]; v.y = acc[2];
        *(ulonglong2*)(zr + (size_t)r0 * 64 + cb0) = v;
        v.x = acc[4]; v.y = acc[6];
        *(ulonglong2*)(zr + (size_t)r0 * 64 + cb0 + 4) = v;
        v.x = acc[1]; v.y = acc[3];
        *(ulonglong2*)(zr + (size_t)(r0 + 1) * 64 + cb0) = v;
        v.x = acc[5]; v.y = acc[7];
        *(ulonglong2*)(zr + (size_t)(r0 + 1) * 64 + cb0 + 4) = v;
    }

    // ---- split-K arrival; last CTA runs the cell epilogue ----
    __threadfence();
    __syncthreads();
    if (tid == 0) {
        int old = atomicAdd(&g_cnt[blk], 1);
        s_last = (old == 3);
        if (old == 3) g_cnt[blk] = 0;     // self-clean for next stage/replay
    }
    __syncthreads();
    if (!s_last) return;
    __threadfence();

    // thread: 1 row x 4 adjacent hcols (hq*4..+3); 64 rows x 4 quads = 256 threads
    {
        int row = tid >> 2, hq = tid & 3;
        float zz[4][4];
        #pragma unroll
        for (int g = 0; g < 4; ++g) {
            float4 s0 = *(const float4*)(zp + ((((size_t)0 * 64 + blk) * 64 + row) * 64) + g * 16 + hq * 4);
            float4 s1 = *(const float4*)(zp + ((((size_t)1 * 64 + blk) * 64 + row) * 64) + g * 16 + hq * 4);
            float4 s2 = *(const float4*)(zp + ((((size_t)2 * 64 + blk) * 64 + row) * 64) + g * 16 + hq * 4);
            float4 s3 = *(const float4*)(zp + ((((size_t)3 * 64 + blk) * 64 + row) * 64) + g * 16 + hq * 4);
            zz[g][0] = ((s0.x + s1.x) + s2.x) + s3.x;
            zz[g][1] = ((s0.y + s1.y) + s2.y) + s3.y;
            zz[g][2] = ((s0.z + s1.z) + s2.z) + s3.z;
            zz[g][3] = ((s0.w + s1.w) + s2.w) + s3.w;
        }
        #pragma unroll
        for (int j = 0; j < 4; ++j) {
            int hcol = blk * 16 + hq * 4 + j;
            float cv = cst[hcol * 64 + row];
            float fg = sigm (zz[0][j] + bias[hcol]        + wc[hcol]        * cv);
            float ig = sigm (zz[1][j] + bias[1024 + hcol] + wc[1024 + hcol] * cv);
            float gg = tanhf(zz[2][j] + bias[2048 + hcol] + wc[2048 + hcol] * cv);
            float og = sigm (zz[3][j] + bias[3072 + hcol] + wc[3072 + hcol] * cv);
            float cn = fg * cv + ig * gg;
            float hv = og * tanhf(cn);
            cst[hcol * 64 + row] = cn;
            *(float2*)&hdup[(size_t)hcol * 128 + 2 * row] = make_float2(hv, hv);
            if (outdup) outdup[hcol * 64 + row] = hv;
        }
    }
}

// ---------------- final projection ----------------
// out[t][b][d] = sigmoid( sum_k outs[t][k][b] * finW[k][d] + finb[d] )
__global__ void __launch_bounds__(256, 1) final_proj(
    const float* __restrict__ outs, const float* __restrict__ W,
    const float* __restrict__ bvec, float* __restrict__ out)
{
    __shared__ __align__(16) float Ash[KC][64];
    __shared__ __align__(16) float Wsh[KC][64];
    const int t = blockIdx.y, dq = blockIdx.x;
    const int tid = threadIdx.x;
    const int dc = tid & 63, rg = tid >> 6;
    const float* abase = outs + (size_t)t * 65536;

    U64 acc[8];
    #pragma unroll
    for (int qq = 0; qq < 8; ++qq) acc[qq] = 0;

    for (int kb = 0; kb < 1024; kb += KC) {
        __syncthreads();
        #pragma unroll
        for (int j = 0; j < 2; ++j) {
            int i = tid + j * 256;
            int k = i >> 4, m4 = (i & 15) << 2;
            *(float4*)&Ash[k][m4] = *(const float4*)(abase + (size_t)(kb + k) * 64 + m4);
            *(float4*)&Wsh[k][m4] = *(const float4*)(W + (size_t)(kb + k) * 256 + dq * 64 + m4);
        }
        __syncthreads();
        #pragma unroll
        for (int k = 0; k < KC; ++k) {
            U64 wd = dupf(Wsh[k][dc]);
            const ulonglong2* ap = (const ulonglong2*)&Ash[k][rg * 16];
            #pragma unroll
            for (int qq = 0; qq < 4; ++qq) {
                ulonglong2 u = ap[qq];
                acc[2 * qq]     = fma2(u.x, wd, acc[2 * qq]);
                acc[2 * qq + 1] = fma2(u.y, wd, acc[2 * qq + 1]);
            }
        }
    }

    int dg = dq * 64 + dc;
    float bb = bvec[dg];
    #pragma unroll
    for (int qq = 0; qq < 8; ++qq) {
        float lo, hi; unpk(acc[qq], lo, hi);
        int r0 = rg * 16 + 2 * qq;
        out[((size_t)t * 64 + r0)     * 256 + dg] = sigm(lo + bb);
        out[((size_t)t * 64 + r0 + 1) * 256 + dg] = sigm(hi + bb);
    }
}

// ---------------- host driver ----------------
extern "C" void kernel_launch(void* const* d_in, const int* in_sizes, int n_in,
                              void* d_out, int out_size)
{
    const float* x    = (const float*)d_in[0];
    const float* eWx0 = (const float*)d_in[1];
    const float* eWh0 = (const float*)d_in[2];
    const float* eWc0 = (const float*)d_in[3];
    const float* eb0  = (const float*)d_in[4];
    const float* eWx  = (const float*)d_in[5];
    const float* eWh  = (const float*)d_in[6];
    const float* eWc  = (const float*)d_in[7];
    const float* eb   = (const float*)d_in[8];
    const float* dWx  = (const float*)d_in[9];
    const float* dWh  = (const float*)d_in[10];
    const float* dWc  = (const float*)d_in[11];
    const float* db   = (const float*)d_in[12];
    const float* fW   = (const float*)d_in[13];
    const float* fb   = (const float*)d_in[14];
    const float* h0   = (const float*)d_in[15];
    const float* c0   = (const float*)d_in[16];

    float *xT, *hb, *cb, *zb, *ob;
    cudaGetSymbolAddress((void**)&xT, g_xT);
    cudaGetSymbolAddress((void**)&hb, g_h);
    cudaGetSymbolAddress((void**)&cb, g_c);
    cudaGetSymbolAddress((void**)&zb, g_z);
    cudaGetSymbolAddress((void**)&ob, g_outs);

    const int SMEM = (3 * KC * 128 + 3 * KC * 64) * 4;   // 73728 B
    static int attr_done = 0;
    cudaFuncSetAttribute(lstm_gemm, cudaFuncAttributeMaxDynamicSharedMemorySize, SMEM);
    (void)attr_done;

    transpose_x<<<4096, 256>>>(x, xT);
    init_hc<<<768, 256>>>(h0, c0, hb, cb);

    const size_t HS  = 65536;                 // 1024 * 64 (c, outs)
    const size_t HD  = 131072;                // 1024 * 128 (h dup)
    const size_t WSZ = 1024ull * 4096;
    float* H0 = hb;
    float* H1 = hb + HD;
    float* H2 = hb + 2 * HD;
    const dim3 gg(64, 4);

    // -------- encoder: 64 steps x 3 layers --------
    for (int t = 0; t < 64; ++t) {
        const float* xin = xT + (size_t)t * 256 * 128;
        lstm_gemm<<<gg, 256, SMEM>>>(xin, eWx0, 256, H0, eWh0, zb,
                                     eWc0, eb0, cb, H0, (float*)0);
        lstm_gemm<<<gg, 256, SMEM>>>(H0, eWx, 1024, H1, eWh, zb,
                                     eWc, eb, cb + HS, H1, (float*)0);
        lstm_gemm<<<gg, 256, SMEM>>>(H1, eWx + WSZ, 1024, H2, eWh + WSZ, zb,
                                     eWc + 4096, eb + 4096, cb + 2 * HS, H2, (float*)0);
    }
    // -------- decoder: 64 steps x 3 layers; layer0 input = previous top h --------
    for (int t = 0; t < 64; ++t) {
        lstm_gemm<<<gg, 256, SMEM>>>(H2, dWx, 1024, H0, dWh, zb,
                                     dWc, db, cb, H0, (float*)0);
        lstm_gemm<<<gg, 256, SMEM>>>(H0, dWx + WSZ, 1024, H1, dWh + WSZ, zb,
                                     dWc + 4096, db + 4096, cb + HS, H1, (float*)0);
        lstm_gemm<<<gg, 256, SMEM>>>(H1, dWx + 2 * WSZ, 1024, H2, dWh + 2 * WSZ, zb,
                                     dWc + 2 * 4096, db + 2 * 4096, cb + 2 * HS, H2,
                                     ob + (size_t)t * HS);
    }

    final_proj<<<dim3(4, 64), 256>>>(ob, fW, fb, (float*)d_out);
}